// round 12
// baseline (speedup 1.0000x reference)
#include <cuda_runtime.h>
#include <cuda_bf16.h>
#include <math.h>
#include <stdint.h>

// ---------------- problem constants ----------------
#define NN 50000      // nodes
#define NE 200000     // edges
#define DIN 768
#define DHID 256
#define DOUT 64
#define NH 4          // heads layer1
#define NEG 0.2f
#define LNEPS 1e-5f

// ---------------- scratch (device globals; no allocation allowed) ----------
__device__ float g_h1[(size_t)NN * DHID];     // layer1 projection (fp32, for agg gather)
__device__ float g_agg1[(size_t)NN * DHID];
__device__ float g_h2[(size_t)NN * DOUT];
__device__ float g_agg2[(size_t)NN * DOUT];
__device__ float g_als1[NN * NH];
__device__ float g_ald1[NN * NH];
__device__ float g_den1[NN * NH];
__device__ float g_als2[NN];
__device__ float g_ald2[NN];
__device__ float g_den2[NN];
__device__ float g_exp1[(size_t)NE * NH];
__device__ float g_exp2[NE];
__device__ int   g_rel[NN];                   // winner edge id (-1 = untouched)
// bf16 hi/lo splits
__device__ uint16_t g_xh[(size_t)NN * DIN];
__device__ uint16_t g_xl[(size_t)NN * DIN];
__device__ uint16_t g_w1h[(size_t)DIN * DHID];
__device__ uint16_t g_w1l[(size_t)DIN * DHID];
__device__ uint16_t g_w2h[(size_t)DHID * DOUT];
__device__ uint16_t g_w2l[(size_t)DHID * DOUT];
__device__ uint16_t g_h1h[(size_t)NN * DHID];  // post-LN/ELU activations, bf16 split
__device__ uint16_t g_h1l[(size_t)NN * DHID];

// ---------------- helpers ---------------------------------------------------
__device__ __forceinline__ uint32_t s2u(const void* p) {
    uint32_t a;
    asm("{ .reg .u64 t; cvta.to.shared.u64 t, %1; cvt.u32.u64 %0, t; }" : "=r"(a) : "l"(p));
    return a;
}
__device__ __forceinline__ void cvt_split2(float e0, float e1, uint32_t& ph, uint32_t& pl) {
    asm("cvt.rn.bf16x2.f32 %0, %1, %2;" : "=r"(ph) : "f"(e1), "f"(e0));
    float h0 = __uint_as_float(ph << 16);
    float h1 = __uint_as_float(ph & 0xffff0000u);
    float l0 = e0 - h0, l1 = e1 - h1;
    asm("cvt.rn.bf16x2.f32 %0, %1, %2;" : "=r"(pl) : "f"(l1), "f"(l0));
}

#define LDSM4(d, addr) \
    asm volatile("ldmatrix.sync.aligned.m8n8.x4.shared.b16 {%0,%1,%2,%3}, [%4];" \
        : "=r"((d)[0]), "=r"((d)[1]), "=r"((d)[2]), "=r"((d)[3]) : "r"(addr))
#define LDSM4T(d, addr) \
    asm volatile("ldmatrix.sync.aligned.m8n8.x4.trans.shared.b16 {%0,%1,%2,%3}, [%4];" \
        : "=r"((d)[0]), "=r"((d)[1]), "=r"((d)[2]), "=r"((d)[3]) : "r"(addr))
#define MMA_BF16(c, a, b0, b1) \
    asm volatile("mma.sync.aligned.m16n8k16.row.col.f32.bf16.bf16.f32 " \
        "{%0,%1,%2,%3}, {%4,%5,%6,%7}, {%8,%9}, {%0,%1,%2,%3};" \
        : "+f"((c)[0]), "+f"((c)[1]), "+f"((c)[2]), "+f"((c)[3]) \
        : "r"((a)[0]), "r"((a)[1]), "r"((a)[2]), "r"((a)[3]), "r"(b0), "r"(b1))
#define CP_ASYNC16(saddr, gptr) \
    asm volatile("cp.async.cg.shared.global [%0], [%1], 16;" \
        :: "r"(saddr), "l"(gptr) : "memory")
#define CP_COMMIT() asm volatile("cp.async.commit_group;" ::: "memory")
#define CP_WAIT1()  asm volatile("cp.async.wait_group 1;" ::: "memory")
#define CP_WAIT0()  asm volatile("cp.async.wait_group 0;" ::: "memory")

// ---------------- init ------------------------------------------------------
__global__ void k_init() {
    int i = blockIdx.x * blockDim.x + threadIdx.x;
    int stride = gridDim.x * blockDim.x;
    for (int j = i; j < NN * DHID; j += stride) g_agg1[j] = 0.f;
    for (int j = i; j < NN * DOUT; j += stride) g_agg2[j] = 0.f;
    for (int j = i; j < NN * NH;   j += stride) g_den1[j] = 0.f;
    for (int j = i; j < NN;        j += stride) { g_den2[j] = 0.f; g_rel[j] = -1; }
}

__global__ void k_winner(const int* __restrict__ src) {
    int e = blockIdx.x * blockDim.x + threadIdx.x;
    if (e < NE) atomicMax(&g_rel[src[e]], e);
}

// ---------------- pre-split: (x + emb[etype[winner]]) -> bf16 hi/lo --------
__global__ void k_split(const float* __restrict__ x, const float* __restrict__ emb,
                        const int* __restrict__ etype) {
    int f = blockIdx.x * blockDim.x + threadIdx.x;   // float4 index
    if (f >= NN * (DIN / 4)) return;
    int row = f / (DIN / 4), c4 = f % (DIN / 4);
    float4 v = *reinterpret_cast<const float4*>(&x[(size_t)row * DIN + c4 * 4]);
    int w = g_rel[row];
    if (w >= 0) {
        int rl = etype[w];
        float4 e = *reinterpret_cast<const float4*>(&emb[(size_t)rl * DIN + c4 * 4]);
        v.x += e.x; v.y += e.y; v.z += e.z; v.w += e.w;
    }
    uint32_t h0, l0, h1, l1;
    cvt_split2(v.x, v.y, h0, l0);
    cvt_split2(v.z, v.w, h1, l1);
    size_t o = (size_t)row * DIN + c4 * 4;
    *reinterpret_cast<uint2*>(&g_xh[o]) = make_uint2(h0, h1);
    *reinterpret_cast<uint2*>(&g_xl[o]) = make_uint2(l0, l1);
}
// split W1 and W2 into bf16 hi/lo
#define W1Q ((DIN * DHID) / 4)
#define W2Q ((DHID * DOUT) / 4)
__global__ void k_splitW(const float* __restrict__ W1, const float* __restrict__ W2) {
    int f = blockIdx.x * blockDim.x + threadIdx.x;
    if (f >= W1Q + W2Q) return;
    const float* srcp;
    uint16_t *dh, *dl;
    size_t off;
    if (f < W1Q) { srcp = W1; off = (size_t)f * 4; dh = g_w1h; dl = g_w1l; }
    else { srcp = W2; off = (size_t)(f - W1Q) * 4; dh = g_w2h; dl = g_w2l; }
    float4 v = *reinterpret_cast<const float4*>(&srcp[off]);
    uint32_t h0, l0, h1, l1;
    cvt_split2(v.x, v.y, h0, l0);
    cvt_split2(v.z, v.w, h1, l1);
    *reinterpret_cast<uint2*>(&dh[off]) = make_uint2(h0, h1);
    *reinterpret_cast<uint2*>(&dl[off]) = make_uint2(l0, l1);
}

// ---------------- GEMM1: 128x256, cp.async 3-stage, bf16-split, fused logits
#define AST 80
#define BST 528
#define ATILE (128 * AST)
#define BTILE (32 * BST)
#define STAGE_B (2 * ATILE + 2 * BTILE)
#define NSTAGE 3
#define G1_SMEM (NSTAGE * STAGE_B)

__global__ void __launch_bounds__(512, 1) k_gemm1_mma(const float* __restrict__ as1,
                                                      const float* __restrict__ ad1) {
    extern __shared__ char smem[];
    const uint32_t sb = s2u(smem);
    const int tid = threadIdx.x;
    const int wid = tid >> 5, lane = tid & 31;
    const int warp_m = wid >> 2;      // 0..3 -> 32-row slice
    const int warp_n = wid & 3;       // 0..3 -> 64-col slice = head
    const int m0 = blockIdx.x * 128;

    const int ar = tid >> 2, ac = tid & 3;
    int arow = m0 + ar; if (arow >= NN) arow = 0;
    const uint16_t* axh = &g_xh[(size_t)arow * DIN + ac * 8];
    const uint16_t* axl = &g_xl[(size_t)arow * DIN + ac * 8];
    const uint32_t a_sts = (uint32_t)(ar * AST + ac * 16);
    const int bk0 = tid >> 5, bc0 = tid & 31;
    const int bk1 = (tid + 512) >> 5, bc1 = tid & 31;
    const uint32_t b_sts0 = (uint32_t)(bk0 * BST + bc0 * 16);
    const uint32_t b_sts1 = (uint32_t)(bk1 * BST + bc1 * 16);

    auto issue = [&](int kt, int st) {
        uint32_t base = sb + (uint32_t)st * STAGE_B;
        int k0 = kt * 32;
        CP_ASYNC16(base + a_sts, axh + k0);
        CP_ASYNC16(base + ATILE + a_sts, axl + k0);
        const uint16_t* wh = &g_w1h[(size_t)k0 * DHID];
        const uint16_t* wl = &g_w1l[(size_t)k0 * DHID];
        CP_ASYNC16(base + 2 * ATILE + b_sts0, wh + (size_t)bk0 * DHID + bc0 * 8);
        CP_ASYNC16(base + 2 * ATILE + b_sts1, wh + (size_t)bk1 * DHID + bc1 * 8);
        CP_ASYNC16(base + 2 * ATILE + BTILE + b_sts0, wl + (size_t)bk0 * DHID + bc0 * 8);
        CP_ASYNC16(base + 2 * ATILE + BTILE + b_sts1, wl + (size_t)bk1 * DHID + bc1 * 8);
    };

    const uint32_t a_lm = (uint32_t)((warp_m * 32 + (lane & 15)) * AST + (lane >> 4) * 16);
    const uint32_t b_lm = (uint32_t)((lane & 15) * BST + (warp_n * 64 + (lane >> 4) * 8) * 2);

    float acc[2][8][4];
#pragma unroll
    for (int mi = 0; mi < 2; mi++)
#pragma unroll
        for (int nf = 0; nf < 8; nf++)
#pragma unroll
            for (int j = 0; j < 4; j++) acc[mi][nf][j] = 0.f;

    issue(0, 0); CP_COMMIT();
    issue(1, 1); CP_COMMIT();

    const int NCHUNK = DIN / 32;   // 24
    for (int kt = 0; kt < NCHUNK; kt++) {
        const int st = kt % NSTAGE;
        CP_WAIT1();
        __syncthreads();
        const uint32_t base = sb + (uint32_t)st * STAGE_B;
        const uint32_t sAh = base + a_lm;
        const uint32_t sAl = base + ATILE + a_lm;
        const uint32_t sBh = base + 2 * ATILE + b_lm;
        const uint32_t sBl = base + 2 * ATILE + BTILE + b_lm;
#pragma unroll
        for (int s = 0; s < 2; s++) {
            uint32_t ah[2][4], al[2][4];
            LDSM4(ah[0], sAh + s * 32);
            LDSM4(ah[1], sAh + 16 * AST + s * 32);
            LDSM4(al[0], sAl + s * 32);
            LDSM4(al[1], sAl + 16 * AST + s * 32);
#pragma unroll
            for (int g = 0; g < 4; g++) {
                uint32_t bh[4], bl[4];
                LDSM4T(bh, sBh + s * (16 * BST) + g * 32);
                LDSM4T(bl, sBl + s * (16 * BST) + g * 32);
#pragma unroll
                for (int mi = 0; mi < 2; mi++) {
                    MMA_BF16(acc[mi][2 * g],     ah[mi], bh[0], bh[1]);
                    MMA_BF16(acc[mi][2 * g],     al[mi], bh[0], bh[1]);
                    MMA_BF16(acc[mi][2 * g],     ah[mi], bl[0], bl[1]);
                    MMA_BF16(acc[mi][2 * g + 1], ah[mi], bh[2], bh[3]);
                    MMA_BF16(acc[mi][2 * g + 1], al[mi], bh[2], bh[3]);
                    MMA_BF16(acc[mi][2 * g + 1], ah[mi], bl[2], bl[3]);
                }
            }
        }
        if (kt + 2 < NCHUNK) issue(kt + 2, (kt + 2) % NSTAGE);
        CP_COMMIT();
    }

    // epilogue: write h1 + fused per-head logits (head = warp_n)
#pragma unroll
    for (int mi = 0; mi < 2; mi++) {
        int r0 = m0 + warp_m * 32 + mi * 16 + (lane >> 2);
        float s0 = 0.f, s1 = 0.f, d0 = 0.f, d1 = 0.f;
#pragma unroll
        for (int nf = 0; nf < 8; nf++) {
            int c = warp_n * 64 + nf * 8 + (lane & 3) * 2;
            if (r0 < NN)
                *reinterpret_cast<float2*>(&g_h1[(size_t)r0 * DHID + c]) =
                    make_float2(acc[mi][nf][0], acc[mi][nf][1]);
            if (r0 + 8 < NN)
                *reinterpret_cast<float2*>(&g_h1[(size_t)(r0 + 8) * DHID + c]) =
                    make_float2(acc[mi][nf][2], acc[mi][nf][3]);
            float a0 = __ldg(&as1[c]), a1 = __ldg(&as1[c + 1]);
            float b0 = __ldg(&ad1[c]), b1 = __ldg(&ad1[c + 1]);
            s0 += acc[mi][nf][0] * a0 + acc[mi][nf][1] * a1;
            d0 += acc[mi][nf][0] * b0 + acc[mi][nf][1] * b1;
            s1 += acc[mi][nf][2] * a0 + acc[mi][nf][3] * a1;
            d1 += acc[mi][nf][2] * b0 + acc[mi][nf][3] * b1;
        }
#pragma unroll
        for (int o = 1; o < 4; o <<= 1) {
            s0 += __shfl_xor_sync(0xffffffffu, s0, o);
            s1 += __shfl_xor_sync(0xffffffffu, s1, o);
            d0 += __shfl_xor_sync(0xffffffffu, d0, o);
            d1 += __shfl_xor_sync(0xffffffffu, d1, o);
        }
        if ((lane & 3) == 0) {
            if (r0 < NN)     { g_als1[r0 * NH + warp_n] = s0; g_ald1[r0 * NH + warp_n] = d0; }
            if (r0 + 8 < NN) { g_als1[(r0 + 8) * NH + warp_n] = s1; g_ald1[(r0 + 8) * NH + warp_n] = d1; }
        }
    }
}

// ---------------- GEMM2: [NN x 64] = h(bf16 split) @ W2, fused logits2 -----
#define A2ST 272                       // 128 k * 2B + 16 pad
#define A2TILE (128 * A2ST)            // 34816
#define B2ST 144                       // 64 n * 2B + 16 pad
#define B2TILE (256 * B2ST)            // 36864
#define G2_SMEM (4 * A2TILE + 2 * B2TILE)   // 212992

__global__ void __launch_bounds__(256, 1) k_gemm2_mma(const float* __restrict__ as2,
                                                      const float* __restrict__ ad2) {
    extern __shared__ char smem[];
    const uint32_t sb = s2u(smem);
    const int tid = threadIdx.x;
    const int wid = tid >> 5, lane = tid & 31;   // warp_m = wid (16 rows)
    const int m0 = blockIdx.x * 128;

    // A cp.async mapping: per stage, per half: 2048 chunks of 16B, 8/thread
    const int ar = tid >> 4, ac = tid & 15;      // base r (0..15 step), c (0..15)
    // B cp.async mapping: per half: 2048 chunks, 8/thread
    const uint32_t bB = sb + 4 * A2TILE;

    auto issueA = [&](int kt, int st) {
        uint32_t base = sb + (uint32_t)st * 2 * A2TILE;
        int k0 = kt * 128;
#pragma unroll
        for (int i = 0; i < 8; i++) {
            int r = ar + i * 16;
            int row = m0 + r; if (row >= NN) row = 0;
            uint32_t sts = (uint32_t)(r * A2ST + ac * 16);
            CP_ASYNC16(base + sts, &g_h1h[(size_t)row * DHID + k0 + ac * 8]);
            CP_ASYNC16(base + A2TILE + sts, &g_h1l[(size_t)row * DHID + k0 + ac * 8]);
        }
    };
    auto issueB = [&]() {
#pragma unroll
        for (int i = 0; i < 8; i++) {
            int idx = tid + i * 256;
            int r = idx >> 3, c = idx & 7;
            uint32_t sts = (uint32_t)(r * B2ST + c * 16);
            CP_ASYNC16(bB + sts, &g_w2h[(size_t)r * DOUT + c * 8]);
            CP_ASYNC16(bB + B2TILE + sts, &g_w2l[(size_t)r * DOUT + c * 8]);
        }
    };

    const uint32_t a_lm = (uint32_t)((wid * 16 + (lane & 15)) * A2ST + (lane >> 4) * 16);
    const uint32_t b_lm = (uint32_t)((lane & 15) * B2ST + ((lane >> 4) * 8) * 2);

    float acc[8][4];
#pragma unroll
    for (int nf = 0; nf < 8; nf++)
#pragma unroll
        for (int j = 0; j < 4; j++) acc[nf][j] = 0.f;

    issueB(); issueA(0, 0); CP_COMMIT();
    issueA(1, 1); CP_COMMIT();

#pragma unroll
    for (int kt = 0; kt < 2; kt++) {
        if (kt == 0) CP_WAIT1(); else CP_WAIT0();
        __syncthreads();
        const uint32_t base = sb + (uint32_t)kt * 2 * A2TILE;
        const uint32_t sAh = base + a_lm;
        const uint32_t sAl = base + A2TILE + a_lm;
#pragma unroll
        for (int s = 0; s < 8; s++) {
            uint32_t ah[4], al[4];
            LDSM4(ah, sAh + s * 32);
            LDSM4(al, sAl + s * 32);
            uint32_t brow = (uint32_t)((kt * 128 + s * 16) * B2ST);
#pragma unroll
            for (int g = 0; g < 4; g++) {
                uint32_t bh[4], bl[4];
                LDSM4T(bh, bB + brow + b_lm + g * 32);
                LDSM4T(bl, bB + B2TILE + brow + b_lm + g * 32);
                MMA_BF16(acc[2 * g],     ah, bh[0], bh[1]);
                MMA_BF16(acc[2 * g],     al, bh[0], bh[1]);
                MMA_BF16(acc[2 * g],     ah, bl[0], bl[1]);
                MMA_BF16(acc[2 * g + 1], ah, bh[2], bh[3]);
                MMA_BF16(acc[2 * g + 1], al, bh[2], bh[3]);
                MMA_BF16(acc[2 * g + 1], ah, bl[2], bl[3]);
            }
        }
    }

    // epilogue: write h2 + fused logits2
    int r0 = m0 + wid * 16 + (lane >> 2);
    float s0 = 0.f, s1 = 0.f, d0 = 0.f, d1 = 0.f;
#pragma unroll
    for (int nf = 0; nf < 8; nf++) {
        int c = nf * 8 + (lane & 3) * 2;
        if (r0 < NN)
            *reinterpret_cast<float2*>(&g_h2[(size_t)r0 * DOUT + c]) =
                make_float2(acc[nf][0], acc[nf][1]);
        if (r0 + 8 < NN)
            *reinterpret_cast<float2*>(&g_h2[(size_t)(r0 + 8) * DOUT + c]) =
                make_float2(acc[nf][2], acc[nf][3]);
        float a0 = __ldg(&as2[c]), a1 = __ldg(&as2[c + 1]);
        float b0 = __ldg(&ad2[c]), b1 = __ldg(&ad2[c + 1]);
        s0 += acc[nf][0] * a0 + acc[nf][1] * a1;
        d0 += acc[nf][0] * b0 + acc[nf][1] * b1;
        s1 += acc[nf][2] * a0 + acc[nf][3] * a1;
        d1 += acc[nf][2] * b0 + acc[nf][3] * b1;
    }
#pragma unroll
    for (int o = 1; o < 4; o <<= 1) {
        s0 += __shfl_xor_sync(0xffffffffu, s0, o);
        s1 += __shfl_xor_sync(0xffffffffu, s1, o);
        d0 += __shfl_xor_sync(0xffffffffu, d0, o);
        d1 += __shfl_xor_sync(0xffffffffu, d1, o);
    }
    if ((lane & 3) == 0) {
        if (r0 < NN)     { g_als2[r0] = s0; g_ald2[r0] = d0; }
        if (r0 + 8 < NN) { g_als2[r0 + 8] = s1; g_ald2[r0 + 8] = d1; }
    }
}

// ---------------- layer1 edge exp + denominator (vec4 atomic) --------------
__global__ void k_exp1(const int* __restrict__ src, const int* __restrict__ dst) {
    int e = blockIdx.x * blockDim.x + threadIdx.x;
    if (e >= NE) return;
    int s = src[e], d = dst[e];
    float4 as = *reinterpret_cast<const float4*>(&g_als1[s * NH]);
    float4 ad = *reinterpret_cast<const float4*>(&g_ald1[d * NH]);
    float4 ex;
    float v;
    v = as.x + ad.x; v = v > 0.f ? v : NEG * v; ex.x = expf(v);
    v = as.y + ad.y; v = v > 0.f ? v : NEG * v; ex.y = expf(v);
    v = as.z + ad.z; v = v > 0.f ? v : NEG * v; ex.z = expf(v);
    v = as.w + ad.w; v = v > 0.f ? v : NEG * v; ex.w = expf(v);
    *reinterpret_cast<float4*>(&g_exp1[(size_t)e * NH]) = ex;
    atomicAdd(reinterpret_cast<float4*>(&g_den1[d * NH]), ex);
}
__global__ void k_invden1() {
    int i = blockIdx.x * blockDim.x + threadIdx.x;
    if (i < NN * NH) g_den1[i] = 1.f / g_den1[i];
}

// ---------------- layer1 aggregation: 64 threads/edge ----------------------
__global__ void k_agg1(const int* __restrict__ src, const int* __restrict__ dst) {
    int t = blockIdx.x * blockDim.x + threadIdx.x;
    int e = t >> 6;
    int sub = t & 63;
    if (e >= NE) return;
    int s = src[e], d = dst[e];
    int head = sub >> 4;
    float alpha = g_exp1[(size_t)e * NH + head] * g_den1[d * NH + head];
    float4 v = *reinterpret_cast<const float4*>(&g_h1[(size_t)s * DHID + sub * 4]);
    v.x *= alpha; v.y *= alpha; v.z *= alpha; v.w *= alpha;
    atomicAdd(reinterpret_cast<float4*>(&g_agg1[(size_t)d * DHID + sub * 4]), v);
}

// ---------------- LayerNorm(256)+ELU -> bf16 split activations -------------
__global__ void k_ln1(const float* __restrict__ bias, const float* __restrict__ g,
                      const float* __restrict__ be) {
    int w = (blockIdx.x * blockDim.x + threadIdx.x) >> 5;
    int lane = threadIdx.x & 31;
    if (w >= NN) return;
    const float4* p = reinterpret_cast<const float4*>(&g_agg1[(size_t)w * DHID + lane * 8]);
    const float4* bp = reinterpret_cast<const float4*>(&bias[lane * 8]);
    float4 v0 = p[0], v1 = p[1];
    float4 b0 = bp[0], b1v = bp[1];
    v0.x += b0.x; v0.y += b0.y; v0.z += b0.z; v0.w += b0.w;
    v1.x += b1v.x; v1.y += b1v.y; v1.z += b1v.z; v1.w += b1v.w;
    float s  = v0.x + v0.y + v0.z + v0.w + v1.x + v1.y + v1.z + v1.w;
    float sq = v0.x * v0.x + v0.y * v0.y + v0.z * v0.z + v0.w * v0.w
             + v1.x * v1.x + v1.y * v1.y + v1.z * v1.z + v1.w * v1.w;
#pragma unroll
    for (int off = 16; off > 0; off >>= 1) {
        s  += __shfl_xor_sync(0xffffffffu, s, off);
        sq += __shfl_xor_sync(0xffffffffu, sq, off);
    }
    float mu = s * (1.f / DHID);
    float var = sq * (1.f / DHID) - mu * mu;
    float rstd = rsqrtf(var + LNEPS);
    const float4* gp = reinterpret_cast<const float4*>(&g[lane * 8]);
    const float4* ep = reinterpret_cast<const float4*>(&be[lane * 8]);
    float4 g0 = gp[0], g1v = gp[1], e0 = ep[0], e1 = ep[1];
    float out[8];
    float in[8]  = {v0.x, v0.y, v0.z, v0.w, v1.x, v1.y, v1.z, v1.w};
    float gg[8]  = {g0.x, g0.y, g0.z, g0.w, g1v.x, g1v.y, g1v.z, g1v.w};
    float bb[8]  = {e0.x, e0.y, e0.z, e0.w, e1.x, e1.y, e1.z, e1.w};
#pragma unroll
    for (int i = 0; i < 8; i++) {
        float y = (in[i] - mu) * rstd * gg[i] + bb[i];
        out[i] = y > 0.f ? y : expm1f(y);
    }
    uint32_t h[4], l[4];
    cvt_split2(out[0], out[1], h[0], l[0]);
    cvt_split2(out[2], out[3], h[1], l[1]);
    cvt_split2(out[4], out[5], h[2], l[2]);
    cvt_split2(out[6], out[7], h[3], l[3]);
    size_t o = (size_t)w * DHID + lane * 8;
    *reinterpret_cast<uint4*>(&g_h1h[o]) = make_uint4(h[0], h[1], h[2], h[3]);
    *reinterpret_cast<uint4*>(&g_h1l[o]) = make_uint4(l[0], l[1], l[2], l[3]);
}

// ---------------- layer2 edge exp + denominator ----------------------------
__global__ void k_exp2(const int* __restrict__ src, const int* __restrict__ dst) {
    int e = blockIdx.x * blockDim.x + threadIdx.x;
    if (e >= NE) return;
    int s = src[e], d = dst[e];
    float v = g_als2[s] + g_ald2[d];
    v = v > 0.f ? v : NEG * v;
    float ex = expf(v);
    g_exp2[e] = ex;
    atomicAdd(&g_den2[d], ex);
}
__global__ void k_invden2() {
    int i = blockIdx.x * blockDim.x + threadIdx.x;
    if (i < NN) g_den2[i] = 1.f / g_den2[i];
}

// ---------------- layer2 aggregation: 16 threads/edge ----------------------
__global__ void k_agg2(const int* __restrict__ src, const int* __restrict__ dst) {
    int t = blockIdx.x * blockDim.x + threadIdx.x;
    int e = t >> 4;
    int sub = t & 15;
    if (e >= NE) return;
    int s = src[e], d = dst[e];
    float alpha = g_exp2[e] * g_den2[d];
    float4 v = *reinterpret_cast<const float4*>(&g_h2[(size_t)s * DOUT + sub * 4]);
    v.x *= alpha; v.y *= alpha; v.z *= alpha; v.w *= alpha;
    atomicAdd(reinterpret_cast<float4*>(&g_agg2[(size_t)d * DOUT + sub * 4]), v);
}

// ---------------- final LayerNorm(64) -> d_out -----------------------------
__global__ void k_ln2(const float* __restrict__ bias, const float* __restrict__ g,
                      const float* __restrict__ be, float* __restrict__ out) {
    int w = (blockIdx.x * blockDim.x + threadIdx.x) >> 5;
    int lane = threadIdx.x & 31;
    if (w >= NN) return;
    float2 v = *reinterpret_cast<const float2*>(&g_agg2[(size_t)w * DOUT + lane * 2]);
    float2 b = *reinterpret_cast<const float2*>(&bias[lane * 2]);
    v.x += b.x; v.y += b.y;
    float s = v.x + v.y;
    float sq = v.x * v.x + v.y * v.y;
#pragma unroll
    for (int off = 16; off > 0; off >>= 1) {
        s  += __shfl_xor_sync(0xffffffffu, s, off);
        sq += __shfl_xor_sync(0xffffffffu, sq, off);
    }
    float mu = s * (1.f / DOUT);
    float var = sq * (1.f / DOUT) - mu * mu;
    float rstd = rsqrtf(var + LNEPS);
    float2 gg = *reinterpret_cast<const float2*>(&g[lane * 2]);
    float2 bb = *reinterpret_cast<const float2*>(&be[lane * 2]);
    float2 o;
    o.x = (v.x - mu) * rstd * gg.x + bb.x;
    o.y = (v.y - mu) * rstd * gg.y + bb.y;
    *reinterpret_cast<float2*>(&out[(size_t)w * DOUT + lane * 2]) = o;
}

// ---------------- host launch ----------------------------------------------
extern "C" void kernel_launch(void* const* d_in, const int* in_sizes, int n_in,
                              void* d_out, int out_size) {
    const float* x    = (const float*)d_in[0];
    const int*   ei   = (const int*)d_in[1];   // [2, E]: row0 = src, row1 = dst
    const int*   et   = (const int*)d_in[2];
    const float* emb  = (const float*)d_in[3];
    const float* W1   = (const float*)d_in[4];
    const float* as1  = (const float*)d_in[5];
    const float* ad1  = (const float*)d_in[6];
    const float* b1   = (const float*)d_in[7];
    const float* g1   = (const float*)d_in[8];
    const float* be1  = (const float*)d_in[9];
    const float* W2   = (const float*)d_in[10];
    const float* as2  = (const float*)d_in[11];
    const float* ad2  = (const float*)d_in[12];
    const float* b2   = (const float*)d_in[13];
    const float* g2   = (const float*)d_in[14];
    const float* be2  = (const float*)d_in[15];
    float* out = (float*)d_out;

    const int* src = ei;
    const int* dst = ei + NE;

    cudaFuncSetAttribute(k_gemm1_mma, cudaFuncAttributeMaxDynamicSharedMemorySize, G1_SMEM);
    cudaFuncSetAttribute(k_gemm2_mma, cudaFuncAttributeMaxDynamicSharedMemorySize, G2_SMEM);

    // 1. init scratch
    k_init<<<2048, 256>>>();
    // 2. last-write-wins winner edge per src node
    k_winner<<<(NE + 255) / 256, 256>>>(src);
    // 3. pre-split (x + emb[etype[winner]]) and weights into bf16 hi/lo
    k_split<<<(NN * (DIN / 4) + 255) / 256, 256>>>(x, emb, et);
    k_splitW<<<(W1Q + W2Q + 255) / 256, 256>>>(W1, W2);
    // 4. GEMM1 + fused layer1 logits
    k_gemm1_mma<<<(NN + 127) / 128, 512, G1_SMEM>>>(as1, ad1);
    // 5. layer1 softmax + aggregation
    k_exp1<<<(NE + 255) / 256, 256>>>(src, dst);
    k_invden1<<<(NN * NH + 255) / 256, 256>>>();
    k_agg1<<<(NE * 64) / 256, 256>>>(src, dst);
    // 6. LN + ELU -> bf16 split activations
    k_ln1<<<(NN * 32) / 256, 256>>>(b1, g1, be1);
    // 7. GEMM2 + fused layer2 logits
    k_gemm2_mma<<<(NN + 127) / 128, 256, G2_SMEM>>>(as2, ad2);
    // 8. layer2 softmax + aggregation
    k_exp2<<<(NE + 255) / 256, 256>>>(src, dst);
    k_invden2<<<(NN + 255) / 256, 256>>>();
    k_agg2<<<(NE * 16) / 256, 256>>>(src, dst);
    // 9. final LayerNorm -> d_out
    k_ln2<<<(NN * 32) / 256, 256>>>(b2, g2, be2, out);
}